// round 2
// baseline (speedup 1.0000x reference)
#include <cuda_runtime.h>
#include <cuda_bf16.h>

#define N_NODES 50000
#define NUM_GRAPHS 64
#define ET_MAX (1600000 + N_NODES)

// ---------------- scratch (device globals; no allocations) ----------------
__device__ float    g_XP1[N_NODES * 128];   // x @ W1
__device__ float    g_ALs1[N_NODES * 2];
__device__ float    g_ALd1[N_NODES * 2];
__device__ unsigned g_M1[N_NODES * 2];      // ordered-uint max
__device__ float    g_D1[N_NODES * 2];      // softmax denom
__device__ float    g_EX1[ET_MAX * 2];      // per-edge e then exp
__device__ float    g_H1[N_NODES * 128];    // layer1 output

__device__ float    g_XP2[N_NODES * 64];
__device__ float    g_ALs2[N_NODES];
__device__ float    g_ALd2[N_NODES];
__device__ unsigned g_M2[N_NODES];
__device__ float    g_D2[N_NODES];
__device__ float    g_EX2[ET_MAX];
__device__ float    g_H2[N_NODES * 64];

__device__ float    g_POOL[NUM_GRAPHS * 64];
__device__ float    g_CNT[NUM_GRAPHS];
__device__ float    g_DEC1[NUM_GRAPHS * 64];

// ---------------- helpers ----------------
__device__ __forceinline__ unsigned f2ord(float f) {
    unsigned u = __float_as_uint(f);
    return (u & 0x80000000u) ? ~u : (u | 0x80000000u);
}
__device__ __forceinline__ float ord2f(unsigned u) {
    return (u & 0x80000000u) ? __uint_as_float(u & 0x7fffffffu)
                             : __uint_as_float(~u);
}

// ---------------- init ----------------
__global__ void k_init(const float* __restrict__ b1, const float* __restrict__ b2) {
    long long i = (long long)blockIdx.x * blockDim.x + threadIdx.x;
    if (i < (long long)N_NODES * 128) g_H1[i] = b1[i & 127];
    if (i < (long long)N_NODES * 64)  g_H2[i] = b2[i & 63];
    if (i < N_NODES * 2) { g_M1[i] = 0u; g_D1[i] = 0.f; }
    if (i < N_NODES)     { g_M2[i] = 0u; g_D2[i] = 0.f; }
    if (i < NUM_GRAPHS * 64) g_POOL[i] = 0.f;
    if (i < NUM_GRAPHS)      g_CNT[i]  = 0.f;
}

// ---------------- layer-1 feature GEMM: concat(x) @ W1 -> XP1 [N,128] ------
__global__ void k_gemm1(const float* __restrict__ prot,
                        const float* __restrict__ spat,
                        const float* __restrict__ lri,
                        const float* __restrict__ W1) {
    __shared__ float xs[16][132];
    const int tid  = threadIdx.x;               // 128
    const int base = blockIdx.x * 16;
    for (int idx = tid; idx < 16 * 130; idx += 128) {
        int n = idx / 130, k = idx % 130;
        int node = base + n;
        float v = 0.f;
        if (node < N_NODES) {
            if (k < 64)      v = prot[node * 64 + k];
            else if (k < 66) v = spat[node * 2 + (k - 64)];
            else             v = lri[node * 64 + (k - 66)];
        }
        xs[n][k] = v;
    }
    __syncthreads();
    float acc[16];
#pragma unroll
    for (int n = 0; n < 16; n++) acc[n] = 0.f;
    for (int k = 0; k < 130; k++) {
        float w = W1[k * 128 + tid];
#pragma unroll
        for (int n = 0; n < 16; n++) acc[n] = fmaf(xs[n][k], w, acc[n]);
    }
#pragma unroll
    for (int n = 0; n < 16; n++) {
        int node = base + n;
        if (node < N_NODES) g_XP1[node * 128 + tid] = acc[n];
    }
}

// ---------------- layer-2 feature GEMM: H1 @ W2 -> XP2 [N,64] --------------
__global__ void k_gemm2(const float* __restrict__ W2) {
    __shared__ float xs[16][128];
    const int tid  = threadIdx.x;               // 64
    const int base = blockIdx.x * 16;
    for (int idx = tid; idx < 16 * 128; idx += 64) {
        int n = idx / 128, k = idx % 128;
        int node = base + n;
        xs[n][k] = (node < N_NODES) ? g_H1[node * 128 + k] : 0.f;
    }
    __syncthreads();
    float acc[16];
#pragma unroll
    for (int n = 0; n < 16; n++) acc[n] = 0.f;
    for (int k = 0; k < 128; k++) {
        float w = W2[k * 64 + tid];
#pragma unroll
        for (int n = 0; n < 16; n++) acc[n] = fmaf(xs[n][k], w, acc[n]);
    }
#pragma unroll
    for (int n = 0; n < 16; n++) {
        int node = base + n;
        if (node < N_NODES) g_XP2[node * 64 + tid] = acc[n];
    }
}

// ---------------- attention logits: al = sum_c xp * a  ---------------------
template <int H>
__global__ void k_al(const float* __restrict__ asrc, const float* __restrict__ adst) {
    const int F = H * 64;
    const float* XP  = (H == 2) ? g_XP1  : g_XP2;
    float*       ALs = (H == 2) ? g_ALs1 : g_ALs2;
    float*       ALd = (H == 2) ? g_ALd1 : g_ALd2;
    const int n = blockIdx.x, tid = threadIdx.x;
    float v  = XP[n * F + tid];
    float ps = v * asrc[tid];
    float pd = v * adst[tid];
#pragma unroll
    for (int o = 16; o >= 1; o >>= 1) {
        ps += __shfl_down_sync(0xffffffffu, ps, o);
        pd += __shfl_down_sync(0xffffffffu, pd, o);
    }
    __shared__ float sps[4], spd[4];
    int w = tid >> 5;
    if ((tid & 31) == 0) { sps[w] = ps; spd[w] = pd; }
    __syncthreads();
    if (tid < H) {
        ALs[n * H + tid] = sps[2 * tid] + sps[2 * tid + 1];
        ALd[n * H + tid] = spd[2 * tid] + spd[2 * tid + 1];
    }
}

// ---------------- edge pass A: e = lrelu(al_s[src]+al_d[dst]); seg max -----
template <int H>
__global__ void k_edgeA(const int* __restrict__ ei, int E, int ET) {
    const float* ALs = (H == 2) ? g_ALs1 : g_ALs2;
    const float* ALd = (H == 2) ? g_ALd1 : g_ALd2;
    float*       EX  = (H == 2) ? g_EX1  : g_EX2;
    unsigned*    Mu  = (H == 2) ? g_M1   : g_M2;
    int id = blockIdx.x * blockDim.x + threadIdx.x;
    if (id >= ET * H) return;
    int e = id / H, h = id % H;
    int s, d;
    if (e < E) { s = ei[e]; d = ei[E + e]; }
    else       { s = d = e - E; }
    float x  = ALs[s * H + h] + ALd[d * H + h];
    float ev = (x > 0.f) ? x : 0.2f * x;
    EX[id] = ev;
    atomicMax(&Mu[d * H + h], f2ord(ev));
}

// ---------------- edge pass B: ex = exp(e - m[dst]); seg sum ---------------
template <int H>
__global__ void k_edgeB(const int* __restrict__ ei, int E, int ET) {
    float*          EX = (H == 2) ? g_EX1 : g_EX2;
    const unsigned* Mu = (H == 2) ? g_M1  : g_M2;
    float*          Dn = (H == 2) ? g_D1  : g_D2;
    int id = blockIdx.x * blockDim.x + threadIdx.x;
    if (id >= ET * H) return;
    int e = id / H, h = id % H;
    int d;
    if (e < E) d = ei[E + e];
    else       d = e - E;
    float m  = ord2f(Mu[d * H + h]);
    float ex = __expf(EX[id] - m);
    EX[id] = ex;
    atomicAdd(&Dn[d * H + h], ex);
}

// ---------------- edge pass C: H[dst] += alpha * XP[src] -------------------
// Each edge is served by F/4 lanes; each lane moves one float4.
template <int H>
__global__ void k_agg(const int* __restrict__ ei, int E, int ET) {
    const int F   = H * 64;
    const int VT  = F / 4;            // lanes per edge (32 for H=2, 16 for H=1)
    const int EPB = 256 / VT;         // edges per block (8 / 16)
    const float* EX = (H == 2) ? g_EX1 : g_EX2;
    const float* Dn = (H == 2) ? g_D1  : g_D2;
    const float* XP = (H == 2) ? g_XP1 : g_XP2;
    float*      Out = (H == 2) ? g_H1  : g_H2;

    int lane  = threadIdx.x % VT;
    int eslot = threadIdx.x / VT;
    int e = blockIdx.x * EPB + eslot;
    if (e >= ET) return;
    int s, d;
    if (e < E) { s = ei[e]; d = ei[E + e]; }
    else       { s = d = e - E; }
    int c = lane * 4;
    int h = c >> 6;
    float alpha = EX[e * H + h] / Dn[d * H + h];
    float4 v = *(const float4*)&XP[s * F + c];
    float* o = &Out[d * F + c];
    atomicAdd(o + 0, alpha * v.x);
    atomicAdd(o + 1, alpha * v.y);
    atomicAdd(o + 2, alpha * v.z);
    atomicAdd(o + 3, alpha * v.w);
}

// ---------------- global mean pool ----------------
__global__ void k_pool(const int* __restrict__ batch) {
    int n = blockIdx.x, tid = threadIdx.x;      // 64
    int g = batch[n];
    atomicAdd(&g_POOL[g * 64 + tid], g_H2[n * 64 + tid]);
    if (tid == 0) atomicAdd(&g_CNT[g], 1.f);
}
__global__ void k_pooldiv() {
    int g = blockIdx.x, tid = threadIdx.x;      // 64
    float c = g_CNT[g];
    if (c < 1.f) c = 1.f;
    g_POOL[g * 64 + tid] /= c;
}

// ---------------- decoder MLP ----------------
__global__ void k_dec1(const float* __restrict__ Wd1, const float* __restrict__ bd1) {
    int g = blockIdx.x, tid = threadIdx.x;      // 64
    __shared__ float p[64];
    p[tid] = g_POOL[g * 64 + tid];
    __syncthreads();
    float acc = bd1[tid];
    for (int k = 0; k < 64; k++) acc = fmaf(p[k], Wd1[k * 64 + tid], acc);
    g_DEC1[g * 64 + tid] = fmaxf(acc, 0.f);
}
__global__ void k_dec2(const float* __restrict__ Wd2, const float* __restrict__ bd2,
                       float* __restrict__ out) {
    int g = blockIdx.x, tid = threadIdx.x;      // 32
    __shared__ float dd[64];
    dd[tid]      = g_DEC1[g * 64 + tid];
    dd[tid + 32] = g_DEC1[g * 64 + tid + 32];
    __syncthreads();
    float acc = bd2[tid];
    for (int k = 0; k < 64; k++) acc = fmaf(dd[k], Wd2[k * 32 + tid], acc);
    out[g * 32 + tid] = acc;
}

// ---------------- launch ----------------
extern "C" void kernel_launch(void* const* d_in, const int* in_sizes, int n_in,
                              void* d_out, int out_size) {
    const float* prot  = (const float*)d_in[0];
    const float* spat  = (const float*)d_in[1];
    const float* lri   = (const float*)d_in[2];
    const int*   ei    = (const int*)d_in[3];     // int32 (JAX x64 disabled)
    const int*   batch = (const int*)d_in[4];
    const float* W1   = (const float*)d_in[5];
    const float* as1  = (const float*)d_in[6];
    const float* ad1  = (const float*)d_in[7];
    const float* b1   = (const float*)d_in[8];
    const float* W2   = (const float*)d_in[9];
    const float* as2  = (const float*)d_in[10];
    const float* ad2  = (const float*)d_in[11];
    const float* b2   = (const float*)d_in[12];
    const float* Wd1  = (const float*)d_in[13];
    const float* bd1  = (const float*)d_in[14];
    const float* Wd2  = (const float*)d_in[15];
    const float* bd2  = (const float*)d_in[16];
    float* out = (float*)d_out;

    const int E  = in_sizes[3] / 2;
    const int ET = E + N_NODES;

    {
        long long tot = (long long)N_NODES * 128;
        int grid = (int)((tot + 255) / 256);
        k_init<<<grid, 256>>>(b1, b2);
    }

    // ---- layer 1 (H=2) ----
    k_gemm1<<<(N_NODES + 15) / 16, 128>>>(prot, spat, lri, W1);
    k_al<2><<<N_NODES, 128>>>(as1, ad1);
    k_edgeA<2><<<(ET * 2 + 255) / 256, 256>>>(ei, E, ET);
    k_edgeB<2><<<(ET * 2 + 255) / 256, 256>>>(ei, E, ET);
    k_agg<2><<<(ET + 7) / 8, 256>>>(ei, E, ET);

    // ---- layer 2 (H=1) ----
    k_gemm2<<<(N_NODES + 15) / 16, 64>>>(W2);
    k_al<1><<<N_NODES, 64>>>(as2, ad2);
    k_edgeA<1><<<(ET + 255) / 256, 256>>>(ei, E, ET);
    k_edgeB<1><<<(ET + 255) / 256, 256>>>(ei, E, ET);
    k_agg<1><<<(ET + 15) / 16, 256>>>(ei, E, ET);

    // ---- pool + decoder ----
    k_pool<<<N_NODES, 64>>>(batch);
    k_pooldiv<<<NUM_GRAPHS, 64>>>();
    k_dec1<<<NUM_GRAPHS, 64>>>(Wd1, bd1);
    k_dec2<<<NUM_GRAPHS, 32>>>(Wd2, bd2, out);
}

// round 3
// speedup vs baseline: 2.0656x; 2.0656x over previous
#include <cuda_runtime.h>
#include <cuda_bf16.h>

#define N_NODES 50000
#define NUM_GRAPHS 64
#define ET_MAX (1600000 + N_NODES)

// ---------------- scratch (device globals) ----------------
__device__ float g_XP1[N_NODES * 128];
__device__ float g_ALs1[N_NODES * 2];
__device__ float g_ALd1[N_NODES * 2];
__device__ float g_H1[N_NODES * 128];

__device__ float g_XP2[N_NODES * 64];
__device__ float g_ALs2[N_NODES];
__device__ float g_ALd2[N_NODES];
__device__ float g_H2[N_NODES * 64];

__device__ int g_deg[N_NODES];
__device__ int g_rowptr[N_NODES + 1];
__device__ int g_cursor[N_NODES];
__device__ int g_srcs[ET_MAX];

__device__ float g_POOL[NUM_GRAPHS * 64];
__device__ float g_DEC1[NUM_GRAPHS * 64];

// ---------------- CSR build ----------------
__global__ void k_zero() {
    int i = blockIdx.x * blockDim.x + threadIdx.x;
    if (i < N_NODES) g_deg[i] = 0;
}

__global__ void k_hist(const int* __restrict__ ei, int E, int ET) {
    int e = blockIdx.x * blockDim.x + threadIdx.x;
    if (e >= ET) return;
    int d = (e < E) ? ei[E + e] : (e - E);
    atomicAdd(&g_deg[d], 1);
}

// single-block 2-level scan over 50000 counters -> rowptr (exclusive), cursor copy
__global__ void k_scan() {
    __shared__ int part[1024];
    const int CH = (N_NODES + 1023) / 1024;   // 49
    int t = threadIdx.x;
    int base = t * CH;
    int sum = 0;
    for (int i = 0; i < CH; i++) {
        int idx = base + i;
        if (idx < N_NODES) sum += g_deg[idx];
    }
    part[t] = sum;
    __syncthreads();
    for (int o = 1; o < 1024; o <<= 1) {
        int v = (t >= o) ? part[t - o] : 0;
        __syncthreads();
        part[t] += v;
        __syncthreads();
    }
    int off = (t == 0) ? 0 : part[t - 1];
    for (int i = 0; i < CH; i++) {
        int idx = base + i;
        if (idx < N_NODES) {
            int c = g_deg[idx];
            g_rowptr[idx] = off;
            g_cursor[idx] = off;
            off += c;
        }
    }
    if (t == 1023) g_rowptr[N_NODES] = off;
}

__global__ void k_scatter(const int* __restrict__ ei, int E, int ET) {
    int e = blockIdx.x * blockDim.x + threadIdx.x;
    if (e >= ET) return;
    int d, s;
    if (e < E) { s = ei[e]; d = ei[E + e]; }
    else       { s = d = e - E; }
    int pos = atomicAdd(&g_cursor[d], 1);
    g_srcs[pos] = s;
}

// ---------------- layer-1 feature GEMM: concat(x) @ W1 -> XP1 [N,128] ------
__global__ void k_gemm1(const float* __restrict__ prot,
                        const float* __restrict__ spat,
                        const float* __restrict__ lri,
                        const float* __restrict__ W1) {
    __shared__ float xs[16][132];
    const int tid  = threadIdx.x;               // 128
    const int base = blockIdx.x * 16;
    for (int idx = tid; idx < 16 * 130; idx += 128) {
        int n = idx / 130, k = idx % 130;
        int node = base + n;
        float v = 0.f;
        if (node < N_NODES) {
            if (k < 64)      v = prot[node * 64 + k];
            else if (k < 66) v = spat[node * 2 + (k - 64)];
            else             v = lri[node * 64 + (k - 66)];
        }
        xs[n][k] = v;
    }
    __syncthreads();
    float acc[16];
#pragma unroll
    for (int n = 0; n < 16; n++) acc[n] = 0.f;
    for (int k = 0; k < 130; k++) {
        float w = W1[k * 128 + tid];
#pragma unroll
        for (int n = 0; n < 16; n++) acc[n] = fmaf(xs[n][k], w, acc[n]);
    }
#pragma unroll
    for (int n = 0; n < 16; n++) {
        int node = base + n;
        if (node < N_NODES) g_XP1[node * 128 + tid] = acc[n];
    }
}

// ---------------- layer-2 feature GEMM: H1 @ W2 -> XP2 [N,64] --------------
__global__ void k_gemm2(const float* __restrict__ W2) {
    __shared__ float xs[16][128];
    const int tid  = threadIdx.x;               // 64
    const int base = blockIdx.x * 16;
    for (int idx = tid; idx < 16 * 128; idx += 64) {
        int n = idx / 128, k = idx % 128;
        int node = base + n;
        xs[n][k] = (node < N_NODES) ? g_H1[node * 128 + k] : 0.f;
    }
    __syncthreads();
    float acc[16];
#pragma unroll
    for (int n = 0; n < 16; n++) acc[n] = 0.f;
    for (int k = 0; k < 128; k++) {
        float w = W2[k * 64 + tid];
#pragma unroll
        for (int n = 0; n < 16; n++) acc[n] = fmaf(xs[n][k], w, acc[n]);
    }
#pragma unroll
    for (int n = 0; n < 16; n++) {
        int node = base + n;
        if (node < N_NODES) g_XP2[node * 64 + tid] = acc[n];
    }
}

// ---------------- attention logits ----------------
template <int H>
__global__ void k_al(const float* __restrict__ asrc, const float* __restrict__ adst) {
    const int F = H * 64;
    const float* XP  = (H == 2) ? g_XP1  : g_XP2;
    float*       ALs = (H == 2) ? g_ALs1 : g_ALs2;
    float*       ALd = (H == 2) ? g_ALd1 : g_ALd2;
    const int n = blockIdx.x, tid = threadIdx.x;
    float v  = XP[n * F + tid];
    float ps = v * asrc[tid];
    float pd = v * adst[tid];
#pragma unroll
    for (int o = 16; o >= 1; o >>= 1) {
        ps += __shfl_down_sync(0xffffffffu, ps, o);
        pd += __shfl_down_sync(0xffffffffu, pd, o);
    }
    __shared__ float sps[4], spd[4];
    int w = tid >> 5;
    if ((tid & 31) == 0) { sps[w] = ps; spd[w] = pd; }
    __syncthreads();
    if (tid < H) {
        ALs[n * H + tid] = sps[2 * tid] + sps[2 * tid + 1];
        ALd[n * H + tid] = spd[2 * tid] + spd[2 * tid + 1];
    }
}

// ---------------- fused online-softmax aggregation --------------------------
// One warp per dst node. Lane owns F/32 contiguous channels; per-head
// running (max, denom) kept redundantly per lane. No atomics.
template <int H>
__global__ void k_aggf(const float* __restrict__ bias) {
    const int F  = H * 64;
    const int PC = F / 32;                       // floats per lane: 4 or 2
    const float* XP  = (H == 2) ? g_XP1  : g_XP2;
    const float* ALs = (H == 2) ? g_ALs1 : g_ALs2;
    const float* ALd = (H == 2) ? g_ALd1 : g_ALd2;
    float*       Out = (H == 2) ? g_H1   : g_H2;

    int warp = (blockIdx.x * blockDim.x + threadIdx.x) >> 5;
    int lane = threadIdx.x & 31;
    if (warp >= N_NODES) return;
    const int d  = warp;
    const int c0 = lane * PC;
    const int h  = c0 >> 6;                      // head index for this lane

    const float ald = ALd[d * H + h];
    float m = -1e30f, den = 0.f;
    float acc[4] = {0.f, 0.f, 0.f, 0.f};

    const int r0 = g_rowptr[d], r1 = g_rowptr[d + 1];

    // prefetch first edge
    int   s   = g_srcs[r0];
    float als = ALs[s * H + h];
    float4 v;
    if (PC == 4) v = *(const float4*)&XP[s * F + c0];
    else { float2 t = *(const float2*)&XP[s * F + c0]; v.x = t.x; v.y = t.y; }

    for (int i = r0; i < r1; i++) {
        // prefetch next edge while processing current
        int   sn = 0; float alsn = 0.f; float4 vn = v;
        if (i + 1 < r1) {
            sn   = g_srcs[i + 1];
            alsn = ALs[sn * H + h];
            if (PC == 4) vn = *(const float4*)&XP[sn * F + c0];
            else { float2 t = *(const float2*)&XP[sn * F + c0]; vn.x = t.x; vn.y = t.y; }
        }
        float x  = als + ald;
        float e  = (x > 0.f) ? x : 0.2f * x;
        float nm = fmaxf(m, e);
        float sc = __expf(m - nm);
        float w  = __expf(e - nm);
        acc[0] = acc[0] * sc + w * v.x;
        acc[1] = acc[1] * sc + w * v.y;
        if (PC == 4) {
            acc[2] = acc[2] * sc + w * v.z;
            acc[3] = acc[3] * sc + w * v.w;
        }
        den = den * sc + w;
        m   = nm;
        s = sn; als = alsn; v = vn;
    }

    float inv = 1.f / den;
#pragma unroll
    for (int j = 0; j < PC; j++)
        Out[d * F + c0 + j] = acc[j] * inv + bias[c0 + j];
}

// ---------------- pool via sorted-batch segments ----------------
__global__ void k_pool_seg(const int* __restrict__ batch) {
    int g = blockIdx.x, tid = threadIdx.x;       // 64 threads
    __shared__ int sb[2];
    if (tid < 2) {
        int target = g + tid;
        int lo = 0, hi = N_NODES;
        while (lo < hi) {
            int mid = (lo + hi) >> 1;
            if (batch[mid] < target) lo = mid + 1; else hi = mid;
        }
        sb[tid] = lo;
    }
    __syncthreads();
    int s = sb[0], e = sb[1];
    float acc = 0.f;
    for (int n = s; n < e; n++) acc += g_H2[n * 64 + tid];
    float c = (float)(e - s);
    if (c < 1.f) c = 1.f;
    g_POOL[g * 64 + tid] = acc / c;
}

// ---------------- decoder MLP ----------------
__global__ void k_dec1(const float* __restrict__ Wd1, const float* __restrict__ bd1) {
    int g = blockIdx.x, tid = threadIdx.x;       // 64
    __shared__ float p[64];
    p[tid] = g_POOL[g * 64 + tid];
    __syncthreads();
    float acc = bd1[tid];
    for (int k = 0; k < 64; k++) acc = fmaf(p[k], Wd1[k * 64 + tid], acc);
    g_DEC1[g * 64 + tid] = fmaxf(acc, 0.f);
}
__global__ void k_dec2(const float* __restrict__ Wd2, const float* __restrict__ bd2,
                       float* __restrict__ out) {
    int g = blockIdx.x, tid = threadIdx.x;       // 32
    __shared__ float dd[64];
    dd[tid]      = g_DEC1[g * 64 + tid];
    dd[tid + 32] = g_DEC1[g * 64 + tid + 32];
    __syncthreads();
    float acc = bd2[tid];
    for (int k = 0; k < 64; k++) acc = fmaf(dd[k], Wd2[k * 32 + tid], acc);
    out[g * 32 + tid] = acc;
}

// ---------------- launch ----------------
extern "C" void kernel_launch(void* const* d_in, const int* in_sizes, int n_in,
                              void* d_out, int out_size) {
    const float* prot  = (const float*)d_in[0];
    const float* spat  = (const float*)d_in[1];
    const float* lri   = (const float*)d_in[2];
    const int*   ei    = (const int*)d_in[3];
    const int*   batch = (const int*)d_in[4];
    const float* W1   = (const float*)d_in[5];
    const float* as1  = (const float*)d_in[6];
    const float* ad1  = (const float*)d_in[7];
    const float* b1   = (const float*)d_in[8];
    const float* W2   = (const float*)d_in[9];
    const float* as2  = (const float*)d_in[10];
    const float* ad2  = (const float*)d_in[11];
    const float* b2   = (const float*)d_in[12];
    const float* Wd1  = (const float*)d_in[13];
    const float* bd1  = (const float*)d_in[14];
    const float* Wd2  = (const float*)d_in[15];
    const float* bd2  = (const float*)d_in[16];
    float* out = (float*)d_out;

    const int E  = in_sizes[3] / 2;
    const int ET = E + N_NODES;

    // ---- CSR build (dst-sorted) ----
    k_zero<<<(N_NODES + 255) / 256, 256>>>();
    k_hist<<<(ET + 255) / 256, 256>>>(ei, E, ET);
    k_scan<<<1, 1024>>>();
    k_scatter<<<(ET + 255) / 256, 256>>>(ei, E, ET);

    // ---- layer 1 (H=2) ----
    k_gemm1<<<(N_NODES + 15) / 16, 128>>>(prot, spat, lri, W1);
    k_al<2><<<N_NODES, 128>>>(as1, ad1);
    k_aggf<2><<<(N_NODES + 7) / 8, 256>>>(b1);

    // ---- layer 2 (H=1) ----
    k_gemm2<<<(N_NODES + 15) / 16, 64>>>(W2);
    k_al<1><<<N_NODES, 64>>>(as2, ad2);
    k_aggf<1><<<(N_NODES + 7) / 8, 256>>>(b2);

    // ---- pool + decoder ----
    k_pool_seg<<<NUM_GRAPHS, 64>>>(batch);
    k_dec1<<<NUM_GRAPHS, 64>>>(Wd1, bd1);
    k_dec2<<<NUM_GRAPHS, 32>>>(Wd2, bd2, out);
}

// round 4
// speedup vs baseline: 2.2131x; 1.0715x over previous
#include <cuda_runtime.h>
#include <cuda_bf16.h>

#define N_NODES 50000
#define NUM_GRAPHS 64
#define ET_MAX (1600000 + N_NODES)

// ---------------- scratch (device globals) ----------------
__device__ float g_XP1[N_NODES * 128];
__device__ float g_ALs1[N_NODES * 2];
__device__ float g_ALd1[N_NODES * 2];
__device__ float g_H1[N_NODES * 128];

__device__ float g_XP2[N_NODES * 64];
__device__ float g_ALs2[N_NODES];
__device__ float g_ALd2[N_NODES];
__device__ float g_H2[N_NODES * 64];

__device__ int g_deg[N_NODES];
__device__ int g_rowptr[N_NODES + 1];
__device__ int g_cursor[N_NODES];
__device__ int g_srcs[ET_MAX];

__device__ float g_POOL[NUM_GRAPHS * 64];
__device__ float g_DEC1[NUM_GRAPHS * 64];

// ---------------- CSR build ----------------
__global__ void k_zero() {
    int i = blockIdx.x * blockDim.x + threadIdx.x;
    if (i < N_NODES) g_deg[i] = 0;
}

__global__ void k_hist(const int* __restrict__ ei, int E, int ET) {
    int e = blockIdx.x * blockDim.x + threadIdx.x;
    if (e >= ET) return;
    int d = (e < E) ? ei[E + e] : (e - E);
    atomicAdd(&g_deg[d], 1);
}

__global__ void k_scan() {
    __shared__ int part[1024];
    const int CH = (N_NODES + 1023) / 1024;
    int t = threadIdx.x;
    int base = t * CH;
    int sum = 0;
    for (int i = 0; i < CH; i++) {
        int idx = base + i;
        if (idx < N_NODES) sum += g_deg[idx];
    }
    part[t] = sum;
    __syncthreads();
    for (int o = 1; o < 1024; o <<= 1) {
        int v = (t >= o) ? part[t - o] : 0;
        __syncthreads();
        part[t] += v;
        __syncthreads();
    }
    int off = (t == 0) ? 0 : part[t - 1];
    for (int i = 0; i < CH; i++) {
        int idx = base + i;
        if (idx < N_NODES) {
            int c = g_deg[idx];
            g_rowptr[idx] = off;
            g_cursor[idx] = off;
            off += c;
        }
    }
    if (t == 1023) g_rowptr[N_NODES] = off;
}

__global__ void k_scatter(const int* __restrict__ ei, int E, int ET) {
    int e = blockIdx.x * blockDim.x + threadIdx.x;
    if (e >= ET) return;
    int d, s;
    if (e < E) { s = ei[e]; d = ei[E + e]; }
    else       { s = d = e - E; }
    int pos = atomicAdd(&g_cursor[d], 1);
    g_srcs[pos] = s;
}

// ---------------- layer-1 feature GEMM ----------------
__global__ void k_gemm1(const float* __restrict__ prot,
                        const float* __restrict__ spat,
                        const float* __restrict__ lri,
                        const float* __restrict__ W1) {
    __shared__ float xs[16][132];
    const int tid  = threadIdx.x;               // 128
    const int base = blockIdx.x * 16;
    for (int idx = tid; idx < 16 * 130; idx += 128) {
        int n = idx / 130, k = idx % 130;
        int node = base + n;
        float v = 0.f;
        if (node < N_NODES) {
            if (k < 64)      v = prot[node * 64 + k];
            else if (k < 66) v = spat[node * 2 + (k - 64)];
            else             v = lri[node * 64 + (k - 66)];
        }
        xs[n][k] = v;
    }
    __syncthreads();
    float acc[16];
#pragma unroll
    for (int n = 0; n < 16; n++) acc[n] = 0.f;
    for (int k = 0; k < 130; k++) {
        float w = W1[k * 128 + tid];
#pragma unroll
        for (int n = 0; n < 16; n++) acc[n] = fmaf(xs[n][k], w, acc[n]);
    }
#pragma unroll
    for (int n = 0; n < 16; n++) {
        int node = base + n;
        if (node < N_NODES) g_XP1[node * 128 + tid] = acc[n];
    }
}

// ---------------- layer-2 feature GEMM ----------------
__global__ void k_gemm2(const float* __restrict__ W2) {
    __shared__ float xs[16][128];
    const int tid  = threadIdx.x;               // 64
    const int base = blockIdx.x * 16;
    for (int idx = tid; idx < 16 * 128; idx += 64) {
        int n = idx / 128, k = idx % 128;
        int node = base + n;
        xs[n][k] = (node < N_NODES) ? g_H1[node * 128 + k] : 0.f;
    }
    __syncthreads();
    float acc[16];
#pragma unroll
    for (int n = 0; n < 16; n++) acc[n] = 0.f;
    for (int k = 0; k < 128; k++) {
        float w = W2[k * 64 + tid];
#pragma unroll
        for (int n = 0; n < 16; n++) acc[n] = fmaf(xs[n][k], w, acc[n]);
    }
#pragma unroll
    for (int n = 0; n < 16; n++) {
        int node = base + n;
        if (node < N_NODES) g_XP2[node * 64 + tid] = acc[n];
    }
}

// ---------------- attention logits ----------------
template <int H>
__global__ void k_al(const float* __restrict__ asrc, const float* __restrict__ adst) {
    const int F = H * 64;
    const float* XP  = (H == 2) ? g_XP1  : g_XP2;
    float*       ALs = (H == 2) ? g_ALs1 : g_ALs2;
    float*       ALd = (H == 2) ? g_ALd1 : g_ALd2;
    const int n = blockIdx.x, tid = threadIdx.x;
    float v  = XP[n * F + tid];
    float ps = v * asrc[tid];
    float pd = v * adst[tid];
#pragma unroll
    for (int o = 16; o >= 1; o >>= 1) {
        ps += __shfl_down_sync(0xffffffffu, ps, o);
        pd += __shfl_down_sync(0xffffffffu, pd, o);
    }
    __shared__ float sps[4], spd[4];
    int w = tid >> 5;
    if ((tid & 31) == 0) { sps[w] = ps; spd[w] = pd; }
    __syncthreads();
    if (tid < H) {
        ALs[n * H + tid] = sps[2 * tid] + sps[2 * tid + 1];
        ALd[n * H + tid] = spd[2 * tid] + spd[2 * tid + 1];
    }
}

// ---------------- fused aggregation: exact max pass + 4-chain weighted sum --
// One warp per dst. Phase A: cooperative per-head max over incoming edges.
// Phase B: fixed-max weighted sum with 4 independent accumulator chains.
template <int H>
__global__ void k_aggf(const float* __restrict__ bias) {
    const int F  = H * 64;
    const int PC = F / 32;                       // channels per lane (4 / 2)
    const int G  = 32 / H;                       // lanes per head group (16 / 32)
    const float* XP  = (H == 2) ? g_XP1  : g_XP2;
    const float* ALs = (H == 2) ? g_ALs1 : g_ALs2;
    const float* ALd = (H == 2) ? g_ALd1 : g_ALd2;
    float*       Out = (H == 2) ? g_H1   : g_H2;

    int warp = (blockIdx.x * blockDim.x + threadIdx.x) >> 5;
    int lane = threadIdx.x & 31;
    if (warp >= N_NODES) return;
    const int d   = warp;
    const int h   = (H == 2) ? (lane >> 4) : 0;
    const int sub = lane & (G - 1);

    const float ald = ALd[d * H + h];
    const int r0 = g_rowptr[d], r1 = g_rowptr[d + 1];

    // ---- phase A: exact per-head max (cooperative, G-way) ----
    float m = -1e30f;
    for (int i = r0 + sub; i < r1; i += G) {
        int s = g_srcs[i];
        float x = ALs[s * H + h] + ald;
        float e = (x > 0.f) ? x : 0.2f * x;
        m = fmaxf(m, e);
    }
#pragma unroll
    for (int o = G / 2; o >= 1; o >>= 1)
        m = fmaxf(m, __shfl_xor_sync(0xffffffffu, m, o, G));

    // ---- phase B: weighted sum, 4 independent chains ----
    const int c0 = lane * PC;
    float acc[4][4] = {};
    float den[4] = {0.f, 0.f, 0.f, 0.f};

    int i = r0;
    for (; i + 3 < r1; i += 4) {
        int s0 = g_srcs[i], s1 = g_srcs[i + 1], s2 = g_srcs[i + 2], s3 = g_srcs[i + 3];
        float a0 = ALs[s0 * H + h], a1 = ALs[s1 * H + h];
        float a2 = ALs[s2 * H + h], a3 = ALs[s3 * H + h];
        float4 v0, v1, v2, v3;
        if (PC == 4) {
            v0 = *(const float4*)&XP[s0 * F + c0];
            v1 = *(const float4*)&XP[s1 * F + c0];
            v2 = *(const float4*)&XP[s2 * F + c0];
            v3 = *(const float4*)&XP[s3 * F + c0];
        } else {
            float2 t0 = *(const float2*)&XP[s0 * F + c0];
            float2 t1 = *(const float2*)&XP[s1 * F + c0];
            float2 t2 = *(const float2*)&XP[s2 * F + c0];
            float2 t3 = *(const float2*)&XP[s3 * F + c0];
            v0.x = t0.x; v0.y = t0.y; v1.x = t1.x; v1.y = t1.y;
            v2.x = t2.x; v2.y = t2.y; v3.x = t3.x; v3.y = t3.y;
        }
        float x0 = a0 + ald, x1 = a1 + ald, x2 = a2 + ald, x3 = a3 + ald;
        float e0 = (x0 > 0.f) ? x0 : 0.2f * x0;
        float e1 = (x1 > 0.f) ? x1 : 0.2f * x1;
        float e2 = (x2 > 0.f) ? x2 : 0.2f * x2;
        float e3 = (x3 > 0.f) ? x3 : 0.2f * x3;
        float w0 = __expf(e0 - m), w1 = __expf(e1 - m);
        float w2 = __expf(e2 - m), w3 = __expf(e3 - m);
        acc[0][0] = fmaf(w0, v0.x, acc[0][0]); acc[0][1] = fmaf(w0, v0.y, acc[0][1]);
        acc[1][0] = fmaf(w1, v1.x, acc[1][0]); acc[1][1] = fmaf(w1, v1.y, acc[1][1]);
        acc[2][0] = fmaf(w2, v2.x, acc[2][0]); acc[2][1] = fmaf(w2, v2.y, acc[2][1]);
        acc[3][0] = fmaf(w3, v3.x, acc[3][0]); acc[3][1] = fmaf(w3, v3.y, acc[3][1]);
        if (PC == 4) {
            acc[0][2] = fmaf(w0, v0.z, acc[0][2]); acc[0][3] = fmaf(w0, v0.w, acc[0][3]);
            acc[1][2] = fmaf(w1, v1.z, acc[1][2]); acc[1][3] = fmaf(w1, v1.w, acc[1][3]);
            acc[2][2] = fmaf(w2, v2.z, acc[2][2]); acc[2][3] = fmaf(w2, v2.w, acc[2][3]);
            acc[3][2] = fmaf(w3, v3.z, acc[3][2]); acc[3][3] = fmaf(w3, v3.w, acc[3][3]);
        }
        den[0] += w0; den[1] += w1; den[2] += w2; den[3] += w3;
    }
    for (; i < r1; i++) {
        int s = g_srcs[i];
        float a = ALs[s * H + h];
        float x = a + ald;
        float e = (x > 0.f) ? x : 0.2f * x;
        float w = __expf(e - m);
        if (PC == 4) {
            float4 v = *(const float4*)&XP[s * F + c0];
            acc[0][0] = fmaf(w, v.x, acc[0][0]); acc[0][1] = fmaf(w, v.y, acc[0][1]);
            acc[0][2] = fmaf(w, v.z, acc[0][2]); acc[0][3] = fmaf(w, v.w, acc[0][3]);
        } else {
            float2 v = *(const float2*)&XP[s * F + c0];
            acc[0][0] = fmaf(w, v.x, acc[0][0]); acc[0][1] = fmaf(w, v.y, acc[0][1]);
        }
        den[0] += w;
    }

    float dt  = (den[0] + den[1]) + (den[2] + den[3]);
    float inv = 1.f / dt;
#pragma unroll
    for (int j = 0; j < PC; j++) {
        float a = (acc[0][j] + acc[1][j]) + (acc[2][j] + acc[3][j]);
        Out[d * F + c0 + j] = a * inv + bias[c0 + j];
    }
}

// ---------------- pool via sorted-batch segments ----------------
__global__ void k_pool_seg(const int* __restrict__ batch) {
    int g = blockIdx.x, tid = threadIdx.x;       // 64 threads
    __shared__ int sb[2];
    if (tid < 2) {
        int target = g + tid;
        int lo = 0, hi = N_NODES;
        while (lo < hi) {
            int mid = (lo + hi) >> 1;
            if (batch[mid] < target) lo = mid + 1; else hi = mid;
        }
        sb[tid] = lo;
    }
    __syncthreads();
    int s = sb[0], e = sb[1];
    float acc = 0.f;
    for (int n = s; n < e; n++) acc += g_H2[n * 64 + tid];
    float c = (float)(e - s);
    if (c < 1.f) c = 1.f;
    g_POOL[g * 64 + tid] = acc / c;
}

// ---------------- decoder MLP ----------------
__global__ void k_dec1(const float* __restrict__ Wd1, const float* __restrict__ bd1) {
    int g = blockIdx.x, tid = threadIdx.x;       // 64
    __shared__ float p[64];
    p[tid] = g_POOL[g * 64 + tid];
    __syncthreads();
    float acc = bd1[tid];
    for (int k = 0; k < 64; k++) acc = fmaf(p[k], Wd1[k * 64 + tid], acc);
    g_DEC1[g * 64 + tid] = fmaxf(acc, 0.f);
}
__global__ void k_dec2(const float* __restrict__ Wd2, const float* __restrict__ bd2,
                       float* __restrict__ out) {
    int g = blockIdx.x, tid = threadIdx.x;       // 32
    __shared__ float dd[64];
    dd[tid]      = g_DEC1[g * 64 + tid];
    dd[tid + 32] = g_DEC1[g * 64 + tid + 32];
    __syncthreads();
    float acc = bd2[tid];
    for (int k = 0; k < 64; k++) acc = fmaf(dd[k], Wd2[k * 32 + tid], acc);
    out[g * 32 + tid] = acc;
}

// ---------------- launch ----------------
extern "C" void kernel_launch(void* const* d_in, const int* in_sizes, int n_in,
                              void* d_out, int out_size) {
    const float* prot  = (const float*)d_in[0];
    const float* spat  = (const float*)d_in[1];
    const float* lri   = (const float*)d_in[2];
    const int*   ei    = (const int*)d_in[3];
    const int*   batch = (const int*)d_in[4];
    const float* W1   = (const float*)d_in[5];
    const float* as1  = (const float*)d_in[6];
    const float* ad1  = (const float*)d_in[7];
    const float* b1   = (const float*)d_in[8];
    const float* W2   = (const float*)d_in[9];
    const float* as2  = (const float*)d_in[10];
    const float* ad2  = (const float*)d_in[11];
    const float* b2   = (const float*)d_in[12];
    const float* Wd1  = (const float*)d_in[13];
    const float* bd1  = (const float*)d_in[14];
    const float* Wd2  = (const float*)d_in[15];
    const float* bd2  = (const float*)d_in[16];
    float* out = (float*)d_out;

    const int E  = in_sizes[3] / 2;
    const int ET = E + N_NODES;

    // ---- CSR build ----
    k_zero<<<(N_NODES + 255) / 256, 256>>>();
    k_hist<<<(ET + 255) / 256, 256>>>(ei, E, ET);
    k_scan<<<1, 1024>>>();
    k_scatter<<<(ET + 255) / 256, 256>>>(ei, E, ET);

    // ---- layer 1 (H=2) ----
    k_gemm1<<<(N_NODES + 15) / 16, 128>>>(prot, spat, lri, W1);
    k_al<2><<<N_NODES, 128>>>(as1, ad1);
    k_aggf<2><<<(N_NODES + 7) / 8, 256>>>(b1);

    // ---- layer 2 (H=1) ----
    k_gemm2<<<(N_NODES + 15) / 16, 64>>>(W2);
    k_al<1><<<N_NODES, 64>>>(as2, ad2);
    k_aggf<1><<<(N_NODES + 7) / 8, 256>>>(b2);

    // ---- pool + decoder ----
    k_pool_seg<<<NUM_GRAPHS, 64>>>(batch);
    k_dec1<<<NUM_GRAPHS, 64>>>(Wd1, bd1);
    k_dec2<<<NUM_GRAPHS, 32>>>(Wd2, bd2, out);
}